// round 4
// baseline (speedup 1.0000x reference)
#include <cuda_runtime.h>
#include <cstdint>
#include <cstddef>

#define TT 256
#define BB 64
#define DD 512
#define HH 1024
#define GG 4096
#define EPSB 1e-5f

// ---------------- scratch (device globals: no allocation allowed) ----------------
__device__ float g_xw[(size_t)TT * BB * GG];   // 256 MB: x@w_ih (BN'd in place)
__device__ float g_y0[(size_t)TT * BB * HH];   // 64 MB: layer-0 output
__device__ float g_h[2][BB * HH];              // ping-pong hidden state
__device__ float g_c[BB * HH];                 // cell state (in-place)
__device__ float g_wpack[HH * GG];             // per-block packed recurrent weights

// ---------------- packed f32x2 helpers ----------------
__device__ __forceinline__ unsigned long long pk2(float lo, float hi) {
    unsigned long long r;
    asm("mov.b64 %0, {%1, %2};" : "=l"(r) : "f"(lo), "f"(hi));
    return r;
}
__device__ __forceinline__ void fma2(unsigned long long& d, unsigned long long a, unsigned long long b) {
    asm("fma.rn.f32x2 %0, %1, %2, %3;" : "=l"(d) : "l"(a), "l"(b), "l"(d));
}
__device__ __forceinline__ float2 upk2(unsigned long long v) {
    float lo, hi;
    asm("mov.b64 {%0, %1}, %2;" : "=f"(lo), "=f"(hi) : "l"(v));
    return make_float2(lo, hi);
}
__device__ __forceinline__ float sigf(float x) { return 1.f / (1.f + __expf(-x)); }

// 2 row-pairs (packed) x 4 cols micro-tile: 16 MACs in 8 fma2 + 4 packs
__device__ __forceinline__ void mma16(unsigned long long acc[2][4], ulonglong2 av, float4 wv) {
    unsigned long long w0 = pk2(wv.x, wv.x), w1 = pk2(wv.y, wv.y),
                       w2 = pk2(wv.z, wv.z), w3 = pk2(wv.w, wv.w);
    fma2(acc[0][0], av.x, w0); fma2(acc[1][0], av.y, w0);
    fma2(acc[0][1], av.x, w1); fma2(acc[1][1], av.y, w1);
    fma2(acc[0][2], av.x, w2); fma2(acc[1][2], av.y, w2);
    fma2(acc[0][3], av.x, w3); fma2(acc[1][3], av.y, w3);
}

// ---------------- input GEMM: g_xw = A(16384 x K) @ W(K x 4096) ----------------
// 64x64 block tile, 256 threads, 4x4 thread tile (2 packed row-pairs x 4 cols),
// double-buffered smem + register prefetch.
__global__ __launch_bounds__(256, 2) void gemm_xw_kernel(const float* __restrict__ A,
                                                         const float* __restrict__ W, int K) {
    __shared__ __align__(16) float As[2][16][68];  // [k][m], transposed
    __shared__ __align__(16) float Bs[2][16][68];  // [k][n]
    const int n0 = blockIdx.x * 64, m0 = blockIdx.y * 64;
    const int tid = threadIdx.x;
    const int mt = tid & 15, nt = tid >> 4;
    const int r0 = mt * 4, c0 = nt * 4;
    const int lm = tid >> 2, lk = (tid & 3) * 4;   // A loader: row lm, 4 k's
    const int bk = tid >> 4, bn = (tid & 15) * 4;  // B loader: row bk, 4 n's
    const float* pA = A + (size_t)(m0 + lm) * K + lk;
    const float* pB = W + (size_t)bk * GG + n0 + bn;

    unsigned long long acc[2][4] = {};

    float4 va = *(const float4*)pA;
    float4 vb = *(const float4*)pB;
    As[0][lk + 0][lm] = va.x; As[0][lk + 1][lm] = va.y;
    As[0][lk + 2][lm] = va.z; As[0][lk + 3][lm] = va.w;
    *(float4*)&Bs[0][bk][bn] = vb;
    __syncthreads();

    int buf = 0;
    for (int k0 = 16; k0 <= K; k0 += 16) {
        const bool more = (k0 < K);
        if (more) {
            va = *(const float4*)(pA + k0);
            vb = *(const float4*)(pB + (size_t)k0 * GG);
        }
#pragma unroll
        for (int k = 0; k < 16; k++) {
            ulonglong2 av = *(const ulonglong2*)&As[buf][k][r0];
            float4 wv = *(const float4*)&Bs[buf][k][c0];
            mma16(acc, av, wv);
        }
        if (more) {
            int nb = buf ^ 1;
            As[nb][lk + 0][lm] = va.x; As[nb][lk + 1][lm] = va.y;
            As[nb][lk + 2][lm] = va.z; As[nb][lk + 3][lm] = va.w;
            *(float4*)&Bs[nb][bk][bn] = vb;
            __syncthreads();
            buf = nb;
        }
    }
#pragma unroll
    for (int rp = 0; rp < 2; rp++) {
        float2 u0 = upk2(acc[rp][0]), u1 = upk2(acc[rp][1]),
               u2 = upk2(acc[rp][2]), u3 = upk2(acc[rp][3]);
        *(float4*)&g_xw[(size_t)(m0 + r0 + 2 * rp) * GG + n0 + c0] =
            make_float4(u0.x, u1.x, u2.x, u3.x);
        *(float4*)&g_xw[(size_t)(m0 + r0 + 2 * rp + 1) * GG + n0 + c0] =
            make_float4(u0.y, u1.y, u2.y, u3.y);
    }
}

// ---------------- BN over batch of x@w_ih, in place; folds bias + beta ----------------
__global__ void bnx_kernel(const float* __restrict__ gamma, const float* __restrict__ beta,
                           const float* __restrict__ bias) {
    const int col = blockIdx.x * 256 + threadIdx.x;
    const int t = blockIdx.y;
    float* base = g_xw + (size_t)t * BB * GG + col;
    float s = 0.f, s2 = 0.f;
#pragma unroll 8
    for (int b = 0; b < BB; b++) {
        float v = base[(size_t)b * GG];
        s += v; s2 += v * v;
    }
    float mu = s * (1.f / BB);
    float var = fmaxf(s2 * (1.f / BB) - mu * mu, 0.f);
    float sc = gamma[col] * rsqrtf(var + EPSB);
    float sh = beta[col] + bias[col] - mu * sc;
#pragma unroll 8
    for (int b = 0; b < BB; b++) {
        size_t o = (size_t)b * GG;
        base[o] = base[o] * sc + sh;
    }
}

// ---------------- pack w_hh so block blk owns gate cols {g*H + blk*8 + j} ----------------
__global__ void pack_w_kernel(const float* __restrict__ w) {
    const int idx = blockIdx.x * 256 + threadIdx.x;  // < HH*GG
    const int c = idx & 31;
    const int k = (idx >> 5) & (HH - 1);
    const int blk = idx >> 15;
    const int gate = c >> 3, j = c & 7;
    g_wpack[idx] = w[(size_t)k * GG + gate * HH + blk * 8 + j];
}

__global__ void init_hc_kernel() {
    const int i = blockIdx.x * 256 + threadIdx.x;
    if (i < BB * HH) { g_h[0][i] = 0.f; g_h[1][i] = 0.f; g_c[i] = 0.f; }
}

__global__ void copy_hc_kernel(float* __restrict__ oh, float* __restrict__ oc) {
    const int i = blockIdx.x * 256 + threadIdx.x;
    if (i < BB * HH) { oh[i] = g_h[0][i]; oc[i] = g_c[i]; }
}

// ---------------- one LSTM timestep ----------------
// 128 blocks; block blk owns h-cols [blk*8, blk*8+8) and gate cols
// {g*1024 + blk*8 + j : g<4, j<8}. All BN stats are block-local.
__global__ __launch_bounds__(128, 1) void lstm_step_kernel(
    int t, int par,
    const float* __restrict__ ghh, const float* __restrict__ bthh,
    const float* __restrict__ gcb, const float* __restrict__ btcb,
    const int* __restrict__ length, float* __restrict__ y_out) {
    __shared__ __align__(16) float hsT[2][32][68];  // [k][b], transposed
    __shared__ __align__(16) float ws[2][32][36];   // [k][c]
    __shared__ __align__(16) float Cs[64][36];      // GEMM result (b, gate-local c)
    __shared__ float redA[8][32];
    __shared__ float redB[8][32];
    __shared__ float scs[32], shs[32];
    __shared__ float c1s[64][9];
    __shared__ float oss[64][9];
    __shared__ float scc[8], shc[8];

    const int blk = blockIdx.x, tid = threadIdx.x;
    const float* hin = g_h[par];
    float* hout = g_h[par ^ 1];
    const float* wp = g_wpack + (size_t)blk * (HH * 32);

    const int rt = tid & 15, ct = tid >> 4;
    const int r0 = rt * 4, c0 = ct * 4;
    unsigned long long acc[2][4] = {};

    // ---- GEMM: Cs(64x32) = hin(64x1024) @ wp(1024x32), chunked K=32, double-buffered ----
    float4 ph[4], pw[2];
#pragma unroll
    for (int i = 0; i < 4; i++) {
        int idx = tid + i * 128;
        ph[i] = *(const float4*)&hin[(idx >> 3) * HH + (idx & 7) * 4];
    }
#pragma unroll
    for (int i = 0; i < 2; i++) {
        int idx = tid + i * 128;
        pw[i] = *(const float4*)&wp[(idx >> 3) * 32 + (idx & 7) * 4];
    }
#pragma unroll
    for (int i = 0; i < 4; i++) {
        int idx = tid + i * 128;
        int b = idx >> 3, kq = (idx & 7) * 4;
        hsT[0][kq + 0][b] = ph[i].x; hsT[0][kq + 1][b] = ph[i].y;
        hsT[0][kq + 2][b] = ph[i].z; hsT[0][kq + 3][b] = ph[i].w;
    }
#pragma unroll
    for (int i = 0; i < 2; i++) {
        int idx = tid + i * 128;
        *(float4*)&ws[0][idx >> 3][(idx & 7) * 4] = pw[i];
    }
    __syncthreads();

    int buf = 0;
    for (int kc = 32; kc <= HH; kc += 32) {
        const bool more = (kc < HH);
        if (more) {
#pragma unroll
            for (int i = 0; i < 4; i++) {
                int idx = tid + i * 128;
                ph[i] = *(const float4*)&hin[(idx >> 3) * HH + kc + (idx & 7) * 4];
            }
#pragma unroll
            for (int i = 0; i < 2; i++) {
                int idx = tid + i * 128;
                pw[i] = *(const float4*)&wp[(kc + (idx >> 3)) * 32 + (idx & 7) * 4];
            }
        }
#pragma unroll
        for (int k = 0; k < 32; k++) {
            ulonglong2 av = *(const ulonglong2*)&hsT[buf][k][r0];
            float4 wv = *(const float4*)&ws[buf][k][c0];
            mma16(acc, av, wv);
        }
        if (more) {
            int nb = buf ^ 1;
#pragma unroll
            for (int i = 0; i < 4; i++) {
                int idx = tid + i * 128;
                int b = idx >> 3, kq = (idx & 7) * 4;
                hsT[nb][kq + 0][b] = ph[i].x; hsT[nb][kq + 1][b] = ph[i].y;
                hsT[nb][kq + 2][b] = ph[i].z; hsT[nb][kq + 3][b] = ph[i].w;
            }
#pragma unroll
            for (int i = 0; i < 2; i++) {
                int idx = tid + i * 128;
                *(float4*)&ws[nb][idx >> 3][(idx & 7) * 4] = pw[i];
            }
            __syncthreads();
            buf = nb;
        }
    }
    __syncthreads();

    // store GEMM result to smem for batch reductions
#pragma unroll
    for (int rp = 0; rp < 2; rp++) {
        float2 u0 = upk2(acc[rp][0]), u1 = upk2(acc[rp][1]),
               u2 = upk2(acc[rp][2]), u3 = upk2(acc[rp][3]);
        *(float4*)&Cs[r0 + 2 * rp][c0]     = make_float4(u0.x, u1.x, u2.x, u3.x);
        *(float4*)&Cs[r0 + 2 * rp + 1][c0] = make_float4(u0.y, u1.y, u2.y, u3.y);
    }
    __syncthreads();

    // ---- BN stats over batch for the 32 gate columns ----
    {
        int c = tid & 31, q = tid >> 5;
        float s = 0.f, s2 = 0.f;
#pragma unroll
        for (int b = q * 16; b < q * 16 + 16; b++) { float v = Cs[b][c]; s += v; s2 += v * v; }
        redA[q][c] = s; redB[q][c] = s2;
    }
    __syncthreads();
    if (tid < 32) {
        float s  = redA[0][tid] + redA[1][tid] + redA[2][tid] + redA[3][tid];
        float s2 = redB[0][tid] + redB[1][tid] + redB[2][tid] + redB[3][tid];
        float mu = s * (1.f / 64.f);
        float var = fmaxf(s2 * (1.f / 64.f) - mu * mu, 0.f);
        int col = (tid >> 3) * HH + blk * 8 + (tid & 7);
        float sc = ghh[col] * rsqrtf(var + EPSB);
        scs[tid] = sc; shs[tid] = bthh[col] - mu * sc;
    }
    __syncthreads();

    // ---- gates + cell update ----
#pragma unroll
    for (int i = 0; i < 4; i++) {
        int idx = tid + i * 128;
        int b = idx >> 3, j = idx & 7;
        const float* bx = g_xw + ((size_t)t * BB + b) * GG + blk * 8 + j;
        float f  = Cs[b][j]      * scs[j]      + shs[j]      + bx[0];
        float ii = Cs[b][8 + j]  * scs[8 + j]  + shs[8 + j]  + bx[HH];
        float oo = Cs[b][16 + j] * scs[16 + j] + shs[16 + j] + bx[2 * HH];
        float gg = Cs[b][24 + j] * scs[24 + j] + shs[24 + j] + bx[3 * HH];
        float cold = g_c[b * HH + blk * 8 + j];
        float c1 = sigf(f) * cold + sigf(ii) * tanhf(gg);
        c1s[b][j] = c1;
        oss[b][j] = sigf(oo);
    }
    __syncthreads();

    // ---- BN stats over batch for the 8 cell columns ----
    if (tid < 64) {
        int j = tid & 7, q = tid >> 3;
        float s = 0.f, s2 = 0.f;
#pragma unroll
        for (int b = q * 8; b < q * 8 + 8; b++) { float v = c1s[b][j]; s += v; s2 += v * v; }
        redA[q][j] = s; redB[q][j] = s2;
    }
    __syncthreads();
    if (tid < 8) {
        float s = 0.f, s2 = 0.f;
#pragma unroll
        for (int q = 0; q < 8; q++) { s += redA[q][tid]; s2 += redB[q][tid]; }
        float mu = s * (1.f / 64.f);
        float var = fmaxf(s2 * (1.f / 64.f) - mu * mu, 0.f);
        int hcol = blk * 8 + tid;
        float sc = gcb[hcol] * rsqrtf(var + EPSB);
        scc[tid] = sc; shc[tid] = btcb[hcol] - mu * sc;
    }
    __syncthreads();

    // ---- h update with length mask; write h, c, y ----
#pragma unroll
    for (int i = 0; i < 4; i++) {
        int idx = tid + i * 128;
        int b = idx >> 3, j = idx & 7;
        int hcol = blk * 8 + j;
        float c1 = c1s[b][j];
        float h1 = oss[b][j] * tanhf(c1 * scc[j] + shc[j]);
        bool m = t < length[b];
        float hold = hin[b * HH + hcol];
        float cold = g_c[b * HH + hcol];
        float hn = m ? h1 : hold;
        float cn = m ? c1 : cold;
        hout[b * HH + hcol] = hn;
        g_c[b * HH + hcol] = cn;
        y_out[((size_t)t * BB + b) * HH + hcol] = hn;
    }
}

// ---------------- host orchestration ----------------
extern "C" void kernel_launch(void* const* d_in, const int* in_sizes, int n_in,
                              void* d_out, int out_size) {
    const float* x     = (const float*)d_in[0];
    const int* length  = (const int*)d_in[1];
    const float* w_ih0 = (const float*)d_in[2];
    const float* w_hh0 = (const float*)d_in[3];
    const float* b0    = (const float*)d_in[4];
    const float* gih0  = (const float*)d_in[5];
    const float* btih0 = (const float*)d_in[6];
    const float* ghh0  = (const float*)d_in[7];
    const float* bthh0 = (const float*)d_in[8];
    const float* gc0   = (const float*)d_in[9];
    const float* btc0  = (const float*)d_in[10];
    const float* w_ih1 = (const float*)d_in[11];
    const float* w_hh1 = (const float*)d_in[12];
    const float* b1    = (const float*)d_in[13];
    const float* gih1  = (const float*)d_in[14];
    const float* btih1 = (const float*)d_in[15];
    const float* ghh1  = (const float*)d_in[16];
    const float* bthh1 = (const float*)d_in[17];
    const float* gc1   = (const float*)d_in[18];
    const float* btc1  = (const float*)d_in[19];

    float* out = (float*)d_out;
    float* y1 = out;
    float* hn = out + (size_t)TT * BB * HH;
    float* cn = hn + 2 * BB * HH;

    float* p_y0 = nullptr;
    cudaGetSymbolAddress((void**)&p_y0, g_y0);

    const dim3 ggrid(GG / 64, (TT * BB) / 64);
    const int hcgrid = (BB * HH) / 256;

    // ---- layer 0 ----
    gemm_xw_kernel<<<ggrid, 256>>>(x, w_ih0, DD);
    bnx_kernel<<<dim3(GG / 256, TT), 256>>>(gih0, btih0, b0);
    pack_w_kernel<<<(HH * GG) / 256, 256>>>(w_hh0);
    init_hc_kernel<<<hcgrid, 256>>>();
    for (int t = 0; t < TT; t++)
        lstm_step_kernel<<<128, 128>>>(t, t & 1, ghh0, bthh0, gc0, btc0, length, p_y0);
    copy_hc_kernel<<<hcgrid, 256>>>(hn, cn);

    // ---- layer 1 ----
    gemm_xw_kernel<<<ggrid, 256>>>(p_y0, w_ih1, HH);
    bnx_kernel<<<dim3(GG / 256, TT), 256>>>(gih1, btih1, b1);
    pack_w_kernel<<<(HH * GG) / 256, 256>>>(w_hh1);
    init_hc_kernel<<<hcgrid, 256>>>();
    for (int t = 0; t < TT; t++)
        lstm_step_kernel<<<128, 128>>>(t, t & 1, ghh1, bthh1, gc1, btc1, length, y1);
    copy_hc_kernel<<<hcgrid, 256>>>(hn + BB * HH, cn + BB * HH);
}

// round 5
// speedup vs baseline: 1.0463x; 1.0463x over previous
#include <cuda_runtime.h>
#include <cstdint>
#include <cstddef>

#define TT 256
#define BB 64
#define DD 512
#define HH 1024
#define GG 4096
#define EPSB 1e-5f

// ---------------- scratch (device globals: no allocation allowed) ----------------
__device__ float g_xw[(size_t)TT * BB * GG];   // 256 MB: x@w_ih (BN'd in place)
__device__ float g_y0[(size_t)TT * BB * HH];   // 64 MB: layer-0 output
__device__ float g_h[2][BB * HH];              // ping-pong hidden state
__device__ float g_c[BB * HH];                 // cell state (in-place)
__device__ float g_wpack[HH * GG];             // per-block packed recurrent weights

// ---------------- packed f32x2 helpers ----------------
__device__ __forceinline__ unsigned long long pk2(float lo, float hi) {
    unsigned long long r;
    asm("mov.b64 %0, {%1, %2};" : "=l"(r) : "f"(lo), "f"(hi));
    return r;
}
__device__ __forceinline__ void fma2(unsigned long long& d, unsigned long long a, unsigned long long b) {
    asm("fma.rn.f32x2 %0, %1, %2, %3;" : "=l"(d) : "l"(a), "l"(b), "l"(d));
}
__device__ __forceinline__ float2 upk2(unsigned long long v) {
    float lo, hi;
    asm("mov.b64 {%0, %1}, %2;" : "=f"(lo), "=f"(hi) : "l"(v));
    return make_float2(lo, hi);
}
__device__ __forceinline__ float sigf(float x) { return 1.f / (1.f + __expf(-x)); }

// 2 row-pairs (packed) x 4 cols micro-tile: 16 MACs in 8 fma2 + 4 packs
__device__ __forceinline__ void mma16(unsigned long long acc[2][4], ulonglong2 av, float4 wv) {
    unsigned long long w0 = pk2(wv.x, wv.x), w1 = pk2(wv.y, wv.y),
                       w2 = pk2(wv.z, wv.z), w3 = pk2(wv.w, wv.w);
    fma2(acc[0][0], av.x, w0); fma2(acc[1][0], av.y, w0);
    fma2(acc[0][1], av.x, w1); fma2(acc[1][1], av.y, w1);
    fma2(acc[0][2], av.x, w2); fma2(acc[1][2], av.y, w2);
    fma2(acc[0][3], av.x, w3); fma2(acc[1][3], av.y, w3);
}

// ---------------- input GEMM: g_xw = A(16384 x K) @ W(K x 4096) ----------------
// 64x64 block tile, 256 threads, 4x4 thread tile (2 packed row-pairs x 4 cols),
// double-buffered smem + register prefetch.
__global__ __launch_bounds__(256, 2) void gemm_xw_kernel(const float* __restrict__ A,
                                                         const float* __restrict__ W, int K) {
    __shared__ __align__(16) float As[2][16][68];  // [k][m], transposed
    __shared__ __align__(16) float Bs[2][16][68];  // [k][n]
    const int n0 = blockIdx.x * 64, m0 = blockIdx.y * 64;
    const int tid = threadIdx.x;
    const int mt = tid & 15, nt = tid >> 4;
    const int r0 = mt * 4, c0 = nt * 4;
    const int lm = tid >> 2, lk = (tid & 3) * 4;   // A loader: row lm, 4 k's
    const int bk = tid >> 4, bn = (tid & 15) * 4;  // B loader: row bk, 4 n's
    const float* pA = A + (size_t)(m0 + lm) * K + lk;
    const float* pB = W + (size_t)bk * GG + n0 + bn;

    unsigned long long acc[2][4] = {};

    float4 va = *(const float4*)pA;
    float4 vb = *(const float4*)pB;
    As[0][lk + 0][lm] = va.x; As[0][lk + 1][lm] = va.y;
    As[0][lk + 2][lm] = va.z; As[0][lk + 3][lm] = va.w;
    *(float4*)&Bs[0][bk][bn] = vb;
    __syncthreads();

    int buf = 0;
    for (int k0 = 16; k0 <= K; k0 += 16) {
        const bool more = (k0 < K);
        if (more) {
            va = *(const float4*)(pA + k0);
            vb = *(const float4*)(pB + (size_t)k0 * GG);
        }
#pragma unroll
        for (int k = 0; k < 16; k++) {
            ulonglong2 av = *(const ulonglong2*)&As[buf][k][r0];
            float4 wv = *(const float4*)&Bs[buf][k][c0];
            mma16(acc, av, wv);
        }
        if (more) {
            int nb = buf ^ 1;
            As[nb][lk + 0][lm] = va.x; As[nb][lk + 1][lm] = va.y;
            As[nb][lk + 2][lm] = va.z; As[nb][lk + 3][lm] = va.w;
            *(float4*)&Bs[nb][bk][bn] = vb;
            __syncthreads();
            buf = nb;
        }
    }
#pragma unroll
    for (int rp = 0; rp < 2; rp++) {
        float2 u0 = upk2(acc[rp][0]), u1 = upk2(acc[rp][1]),
               u2 = upk2(acc[rp][2]), u3 = upk2(acc[rp][3]);
        *(float4*)&g_xw[(size_t)(m0 + r0 + 2 * rp) * GG + n0 + c0] =
            make_float4(u0.x, u1.x, u2.x, u3.x);
        *(float4*)&g_xw[(size_t)(m0 + r0 + 2 * rp + 1) * GG + n0 + c0] =
            make_float4(u0.y, u1.y, u2.y, u3.y);
    }
}

// ---------------- BN over batch of x@w_ih, in place; folds bias + beta ----------------
__global__ void bnx_kernel(const float* __restrict__ gamma, const float* __restrict__ beta,
                           const float* __restrict__ bias) {
    const int col = blockIdx.x * 256 + threadIdx.x;
    const int t = blockIdx.y;
    float* base = g_xw + (size_t)t * BB * GG + col;
    float s = 0.f, s2 = 0.f;
#pragma unroll 8
    for (int b = 0; b < BB; b++) {
        float v = base[(size_t)b * GG];
        s += v; s2 += v * v;
    }
    float mu = s * (1.f / BB);
    float var = fmaxf(s2 * (1.f / BB) - mu * mu, 0.f);
    float sc = gamma[col] * rsqrtf(var + EPSB);
    float sh = beta[col] + bias[col] - mu * sc;
#pragma unroll 8
    for (int b = 0; b < BB; b++) {
        size_t o = (size_t)b * GG;
        base[o] = base[o] * sc + sh;
    }
}

// ---------------- pack w_hh so block blk owns gate cols {g*H + blk*8 + j} ----------------
__global__ void pack_w_kernel(const float* __restrict__ w) {
    const int idx = blockIdx.x * 256 + threadIdx.x;  // < HH*GG
    const int c = idx & 31;
    const int k = (idx >> 5) & (HH - 1);
    const int blk = idx >> 15;
    const int gate = c >> 3, j = c & 7;
    g_wpack[idx] = w[(size_t)k * GG + gate * HH + blk * 8 + j];
}

__global__ void init_hc_kernel() {
    const int i = blockIdx.x * 256 + threadIdx.x;
    if (i < BB * HH) { g_h[0][i] = 0.f; g_h[1][i] = 0.f; g_c[i] = 0.f; }
}

__global__ void copy_hc_kernel(float* __restrict__ oh, float* __restrict__ oc) {
    const int i = blockIdx.x * 256 + threadIdx.x;
    if (i < BB * HH) { oh[i] = g_h[0][i]; oc[i] = g_c[i]; }
}

// ---------------- one LSTM timestep ----------------
// 128 blocks; block blk owns h-cols [blk*8, blk*8+8) and gate cols
// {g*1024 + blk*8 + j : g<4, j<8}. All BN stats are block-local.
__global__ __launch_bounds__(128, 1) void lstm_step_kernel(
    int t, int par,
    const float* __restrict__ ghh, const float* __restrict__ bthh,
    const float* __restrict__ gcb, const float* __restrict__ btcb,
    const int* __restrict__ length, float* __restrict__ y_out) {
    __shared__ __align__(16) float hsT[2][32][68];  // [k][b], transposed
    __shared__ __align__(16) float ws[2][32][36];   // [k][c]
    __shared__ __align__(16) float Cs[64][36];      // GEMM result (b, gate-local c)
    __shared__ float redA[8][32];
    __shared__ float redB[8][32];
    __shared__ float scs[32], shs[32];
    __shared__ float c1s[64][9];
    __shared__ float oss[64][9];
    __shared__ float scc[8], shc[8];

    const int blk = blockIdx.x, tid = threadIdx.x;
    const float* hin = g_h[par];
    float* hout = g_h[par ^ 1];
    const float* wp = g_wpack + (size_t)blk * (HH * 32);

    const int rt = tid & 15, ct = tid >> 4;
    const int r0 = rt * 4, c0 = ct * 4;
    unsigned long long acc[2][4] = {};

    // ---- GEMM: Cs(64x32) = hin(64x1024) @ wp(1024x32), chunked K=32, double-buffered ----
    float4 ph[4], pw[2];
#pragma unroll
    for (int i = 0; i < 4; i++) {
        int idx = tid + i * 128;
        ph[i] = *(const float4*)&hin[(idx >> 3) * HH + (idx & 7) * 4];
    }
#pragma unroll
    for (int i = 0; i < 2; i++) {
        int idx = tid + i * 128;
        pw[i] = *(const float4*)&wp[(idx >> 3) * 32 + (idx & 7) * 4];
    }
#pragma unroll
    for (int i = 0; i < 4; i++) {
        int idx = tid + i * 128;
        int b = idx >> 3, kq = (idx & 7) * 4;
        hsT[0][kq + 0][b] = ph[i].x; hsT[0][kq + 1][b] = ph[i].y;
        hsT[0][kq + 2][b] = ph[i].z; hsT[0][kq + 3][b] = ph[i].w;
    }
#pragma unroll
    for (int i = 0; i < 2; i++) {
        int idx = tid + i * 128;
        *(float4*)&ws[0][idx >> 3][(idx & 7) * 4] = pw[i];
    }
    __syncthreads();

    int buf = 0;
    for (int kc = 32; kc <= HH; kc += 32) {
        const bool more = (kc < HH);
        if (more) {
#pragma unroll
            for (int i = 0; i < 4; i++) {
                int idx = tid + i * 128;
                ph[i] = *(const float4*)&hin[(idx >> 3) * HH + kc + (idx & 7) * 4];
            }
#pragma unroll
            for (int i = 0; i < 2; i++) {
                int idx = tid + i * 128;
                pw[i] = *(const float4*)&wp[(kc + (idx >> 3)) * 32 + (idx & 7) * 4];
            }
        }
#pragma unroll
        for (int k = 0; k < 32; k++) {
            ulonglong2 av = *(const ulonglong2*)&hsT[buf][k][r0];
            float4 wv = *(const float4*)&ws[buf][k][c0];
            mma16(acc, av, wv);
        }
        if (more) {
            int nb = buf ^ 1;
#pragma unroll
            for (int i = 0; i < 4; i++) {
                int idx = tid + i * 128;
                int b = idx >> 3, kq = (idx & 7) * 4;
                hsT[nb][kq + 0][b] = ph[i].x; hsT[nb][kq + 1][b] = ph[i].y;
                hsT[nb][kq + 2][b] = ph[i].z; hsT[nb][kq + 3][b] = ph[i].w;
            }
#pragma unroll
            for (int i = 0; i < 2; i++) {
                int idx = tid + i * 128;
                *(float4*)&ws[nb][idx >> 3][(idx & 7) * 4] = pw[i];
            }
            __syncthreads();
            buf = nb;
        }
    }
    __syncthreads();

    // store GEMM result to smem for batch reductions
#pragma unroll
    for (int rp = 0; rp < 2; rp++) {
        float2 u0 = upk2(acc[rp][0]), u1 = upk2(acc[rp][1]),
               u2 = upk2(acc[rp][2]), u3 = upk2(acc[rp][3]);
        *(float4*)&Cs[r0 + 2 * rp][c0]     = make_float4(u0.x, u1.x, u2.x, u3.x);
        *(float4*)&Cs[r0 + 2 * rp + 1][c0] = make_float4(u0.y, u1.y, u2.y, u3.y);
    }
    __syncthreads();

    // ---- BN stats over batch for the 32 gate columns ----
    {
        int c = tid & 31, q = tid >> 5;
        float s = 0.f, s2 = 0.f;
#pragma unroll
        for (int b = q * 16; b < q * 16 + 16; b++) { float v = Cs[b][c]; s += v; s2 += v * v; }
        redA[q][c] = s; redB[q][c] = s2;
    }
    __syncthreads();
    if (tid < 32) {
        float s  = redA[0][tid] + redA[1][tid] + redA[2][tid] + redA[3][tid];
        float s2 = redB[0][tid] + redB[1][tid] + redB[2][tid] + redB[3][tid];
        float mu = s * (1.f / 64.f);
        float var = fmaxf(s2 * (1.f / 64.f) - mu * mu, 0.f);
        int col = (tid >> 3) * HH + blk * 8 + (tid & 7);
        float sc = ghh[col] * rsqrtf(var + EPSB);
        scs[tid] = sc; shs[tid] = bthh[col] - mu * sc;
    }
    __syncthreads();

    // ---- gates + cell update ----
#pragma unroll
    for (int i = 0; i < 4; i++) {
        int idx = tid + i * 128;
        int b = idx >> 3, j = idx & 7;
        const float* bx = g_xw + ((size_t)t * BB + b) * GG + blk * 8 + j;
        float f  = Cs[b][j]      * scs[j]      + shs[j]      + bx[0];
        float ii = Cs[b][8 + j]  * scs[8 + j]  + shs[8 + j]  + bx[HH];
        float oo = Cs[b][16 + j] * scs[16 + j] + shs[16 + j] + bx[2 * HH];
        float gg = Cs[b][24 + j] * scs[24 + j] + shs[24 + j] + bx[3 * HH];
        float cold = g_c[b * HH + blk * 8 + j];
        float c1 = sigf(f) * cold + sigf(ii) * tanhf(gg);
        c1s[b][j] = c1;
        oss[b][j] = sigf(oo);
    }
    __syncthreads();

    // ---- BN stats over batch for the 8 cell columns ----
    if (tid < 64) {
        int j = tid & 7, q = tid >> 3;
        float s = 0.f, s2 = 0.f;
#pragma unroll
        for (int b = q * 8; b < q * 8 + 8; b++) { float v = c1s[b][j]; s += v; s2 += v * v; }
        redA[q][j] = s; redB[q][j] = s2;
    }
    __syncthreads();
    if (tid < 8) {
        float s = 0.f, s2 = 0.f;
#pragma unroll
        for (int q = 0; q < 8; q++) { s += redA[q][tid]; s2 += redB[q][tid]; }
        float mu = s * (1.f / 64.f);
        float var = fmaxf(s2 * (1.f / 64.f) - mu * mu, 0.f);
        int hcol = blk * 8 + tid;
        float sc = gcb[hcol] * rsqrtf(var + EPSB);
        scc[tid] = sc; shc[tid] = btcb[hcol] - mu * sc;
    }
    __syncthreads();

    // ---- h update with length mask; write h, c, y ----
#pragma unroll
    for (int i = 0; i < 4; i++) {
        int idx = tid + i * 128;
        int b = idx >> 3, j = idx & 7;
        int hcol = blk * 8 + j;
        float c1 = c1s[b][j];
        float h1 = oss[b][j] * tanhf(c1 * scc[j] + shc[j]);
        bool m = t < length[b];
        float hold = hin[b * HH + hcol];
        float cold = g_c[b * HH + hcol];
        float hn = m ? h1 : hold;
        float cn = m ? c1 : cold;
        hout[b * HH + hcol] = hn;
        g_c[b * HH + hcol] = cn;
        y_out[((size_t)t * BB + b) * HH + hcol] = hn;
    }
}

// ---------------- host orchestration ----------------
extern "C" void kernel_launch(void* const* d_in, const int* in_sizes, int n_in,
                              void* d_out, int out_size) {
    const float* x     = (const float*)d_in[0];
    const int* length  = (const int*)d_in[1];
    const float* w_ih0 = (const float*)d_in[2];
    const float* w_hh0 = (const float*)d_in[3];
    const float* b0    = (const float*)d_in[4];
    const float* gih0  = (const float*)d_in[5];
    const float* btih0 = (const float*)d_in[6];
    const float* ghh0  = (const float*)d_in[7];
    const float* bthh0 = (const float*)d_in[8];
    const float* gc0   = (const float*)d_in[9];
    const float* btc0  = (const float*)d_in[10];
    const float* w_ih1 = (const float*)d_in[11];
    const float* w_hh1 = (const float*)d_in[12];
    const float* b1    = (const float*)d_in[13];
    const float* gih1  = (const float*)d_in[14];
    const float* btih1 = (const float*)d_in[15];
    const float* ghh1  = (const float*)d_in[16];
    const float* bthh1 = (const float*)d_in[17];
    const float* gc1   = (const float*)d_in[18];
    const float* btc1  = (const float*)d_in[19];

    float* out = (float*)d_out;
    float* y1 = out;
    float* hn = out + (size_t)TT * BB * HH;
    float* cn = hn + 2 * BB * HH;

    float* p_y0 = nullptr;
    cudaGetSymbolAddress((void**)&p_y0, g_y0);

    const dim3 ggrid(GG / 64, (TT * BB) / 64);
    const int hcgrid = (BB * HH) / 256;

    // ---- layer 0 ----
    gemm_xw_kernel<<<ggrid, 256>>>(x, w_ih0, DD);
    bnx_kernel<<<dim3(GG / 256, TT), 256>>>(gih0, btih0, b0);
    pack_w_kernel<<<(HH * GG) / 256, 256>>>(w_hh0);
    init_hc_kernel<<<hcgrid, 256>>>();
    for (int t = 0; t < TT; t++)
        lstm_step_kernel<<<128, 128>>>(t, t & 1, ghh0, bthh0, gc0, btc0, length, p_y0);
    copy_hc_kernel<<<hcgrid, 256>>>(hn, cn);

    // ---- layer 1 ----
    gemm_xw_kernel<<<ggrid, 256>>>(p_y0, w_ih1, HH);
    bnx_kernel<<<dim3(GG / 256, TT), 256>>>(gih1, btih1, b1);
    pack_w_kernel<<<(HH * GG) / 256, 256>>>(w_hh1);
    init_hc_kernel<<<hcgrid, 256>>>();
    for (int t = 0; t < TT; t++)
        lstm_step_kernel<<<128, 128>>>(t, t & 1, ghh1, bthh1, gc1, btc1, length, y1);
    copy_hc_kernel<<<hcgrid, 256>>>(hn + BB * HH, cn + BB * HH);
}